// round 15
// baseline (speedup 1.0000x reference)
#include <cuda_runtime.h>
#include <cuda_bf16.h>
#include <math.h>
#include <stdint.h>

// ---------------------------------------------------------------- constants
#define BATCH   4096
#define IN_DIM  2048
#define OUT_DIM 4096

#define BM 128
#define BN 128
#define BK 32                    // bf16 elements per stage (64B rows)
#define MATB 8192u               // one 128x32 bf16 matrix in smem
#define STAGE 32768u             // Ah | Al | Bh | Bl
#define SMEM_TOTAL (3 * 32768)   // 96KB dynamic -> 2 CTAs/SM

#define N_PHASES 18
#define TOTAL_TILES 13824

// ---------------------------------------------------------------- state
__device__ float g_acc1[(size_t)BATCH*OUT_DIM];
__device__ float g_acc2[(size_t)BATCH*OUT_DIM];
__device__ float g_a   [(size_t)BATCH*IN_DIM];
__device__ __nv_bfloat16 g_xh [(size_t)BATCH*OUT_DIM];
__device__ __nv_bfloat16 g_xl [(size_t)BATCH*OUT_DIM];
__device__ __nv_bfloat16 g_sh [(size_t)BATCH*IN_DIM];
__device__ __nv_bfloat16 g_sl [(size_t)BATCH*IN_DIM];
__device__ __nv_bfloat16 g_wbh[(size_t)OUT_DIM*IN_DIM];   // W  [4096,2048]  (backward B)
__device__ __nv_bfloat16 g_wbl[(size_t)OUT_DIM*IN_DIM];
__device__ __nv_bfloat16 g_wfh[(size_t)IN_DIM*OUT_DIM];   // W^T [2048,4096] (forward B)
__device__ __nv_bfloat16 g_wfl[(size_t)IN_DIM*OUT_DIM];

__device__ unsigned int g_ticket;
__device__ unsigned int g_bits[N_PHASES][32];   // per (phase,band): bit c = col tile c done

// phase p tile offsets. p0 = UPD0 (1024); p=2i-1 fwd (512), p=2i bwd (1024); p17 = OUT (512)
__constant__ int c_off[N_PHASES + 1] = {
    0, 1024, 1536, 2560, 3072, 4096, 4608, 5632, 6144, 7168,
    7680, 8704, 9216, 10240, 10752, 11776, 12288, 13312, 13824};

// ---------------------------------------------------------------- helpers
__device__ __forceinline__ uint32_t smem_u32(const void* p) {
    uint32_t a;
    asm("{ .reg .u64 t; cvta.to.shared.u64 t, %1; cvt.u32.u64 %0, t; }" : "=r"(a) : "l"(p));
    return a;
}

__device__ __forceinline__ void cp16(uint32_t dst, const void* src) {
    asm volatile("cp.async.cg.shared.global [%0], [%1], 16;" :: "r"(dst), "l"(src));
}

__device__ __forceinline__ uint32_t ldcg(const unsigned int* p) {
    uint32_t v;
    asm volatile("ld.global.cg.u32 %0, [%1];" : "=r"(v) : "l"(p));
    return v;
}

#define MBAR_INIT(addr, cnt) \
    asm volatile("mbarrier.init.shared.b64 [%0], %1;" :: "r"((uint32_t)(addr)), "r"((uint32_t)(cnt)) : "memory")

#define MBAR_ARRIVE(addr) \
    asm volatile("mbarrier.arrive.shared.b64 _, [%0];" :: "r"((uint32_t)(addr)) : "memory")

// .noinc: async completion decrements the base count.
#define CPA_MBAR_ARRIVE(addr) \
    asm volatile("cp.async.mbarrier.arrive.noinc.shared.b64 [%0];" :: "r"((uint32_t)(addr)) : "memory")

#define MBAR_WAIT_PARITY(mbar_smem_addr, phase_parity) do { \
    uint32_t _mbar = (uint32_t)(mbar_smem_addr); \
    uint32_t _parity = (uint32_t)(phase_parity); \
    uint32_t _done; \
    asm volatile( \
        "{\n\t.reg .pred p;\n\t" \
        "mbarrier.try_wait.parity.acquire.cta.shared::cta.b64 p, [%1], %2;\n\t" \
        "selp.b32 %0, 1, 0, p;\n\t}" \
        : "=r"(_done) : "r"(_mbar), "r"(_parity) : "memory"); \
    if (!_done) { \
        asm volatile( \
            "{\n\t.reg .pred P1;\n\t" \
            "WAIT_LOOP_%=:\n\t" \
            "mbarrier.try_wait.parity.acquire.cta.shared::cta.b64 P1, [%0], %1, 0x989680;\n\t" \
            "@P1 bra.uni WAIT_DONE_%=;\n\t" \
            "bra.uni WAIT_LOOP_%=;\n\t" \
            "WAIT_DONE_%=:\n\t}" \
            :: "r"(_mbar), "r"(_parity) : "memory"); \
    } \
} while(0)

__device__ __forceinline__ void ldsm4(uint32_t* d, uint32_t addr) {
    asm volatile("ldmatrix.sync.aligned.m8n8.x4.shared.b16 {%0,%1,%2,%3}, [%4];"
                 : "=r"(d[0]), "=r"(d[1]), "=r"(d[2]), "=r"(d[3]) : "r"(addr));
}

__device__ __forceinline__ void mma16816(float* c, const uint32_t* a, const uint32_t* b) {
    asm volatile("mma.sync.aligned.m16n8k16.row.col.f32.bf16.bf16.f32 "
                 "{%0,%1,%2,%3}, {%4,%5,%6,%7}, {%8,%9}, {%0,%1,%2,%3};"
                 : "+f"(c[0]), "+f"(c[1]), "+f"(c[2]), "+f"(c[3])
                 : "r"(a[0]), "r"(a[1]), "r"(a[2]), "r"(a[3]), "r"(b[0]), "r"(b[1]));
}

__device__ __forceinline__ float bfu(unsigned short u) {
    return __bfloat162float(__ushort_as_bfloat16(u));
}
__device__ __forceinline__ void split2(float v, unsigned short& h, unsigned short& l) {
    __nv_bfloat16 hb = __float2bfloat16_rn(v);
    __nv_bfloat16 lb = __float2bfloat16_rn(v - __bfloat162float(hb));
    h = __bfloat16_as_ushort(hb);
    l = __bfloat16_as_ushort(lb);
}

// ---------------------------------------------------------------- tile info
struct TI {
    const __nv_bfloat16 *Ah, *Al, *Bh, *Bl;
    int p, band, colt, kind, K, N, bm, bn, NSl;
};

__device__ __forceinline__ void decode_t(int t, TI& T) {
    int p = 0;
    while (t >= c_off[p + 1]) ++p;
    const int idx = t - c_off[p];
    const int kind = (p == 0) ? 0 : (p == 17) ? 3 : ((p & 1) ? 1 : 2);
    const bool fwd = (kind == 1) || (kind == 3);
    const int band = fwd ? (idx >> 4) : (idx >> 5);
    T.p = p; T.band = band; T.kind = kind;
    T.colt = idx - (fwd ? (band << 4) : (band << 5));
    T.bm = band * BM; T.bn = T.colt * BN;
    T.K = fwd ? OUT_DIM : IN_DIM;
    T.N = fwd ? IN_DIM : OUT_DIM;
    T.NSl = T.K >> 5;
    if (fwd) { T.Ah = g_xh; T.Al = g_xl; T.Bh = g_wfh; T.Bl = g_wfl; }
    else     { T.Ah = g_sh; T.Al = g_sl; T.Bh = g_wbh; T.Bl = g_wbl; }
}

// dependency gate: wait until producer column bit 'grp' of prev phase is set.
__device__ __forceinline__ void gate_f(const TI& T, int grp, uint32_t& seen) {
    const uint32_t bit = 1u << grp;
    if (seen & bit) return;
    const unsigned int* addr = &g_bits[T.p - 1][T.band];
    uint32_t v = ldcg(addr);
    while (!(v & bit)) { __nanosleep(64); v = ldcg(addr); }
    seen = v;
}

// ---------------------------------------------------------------------------
// Persistent kernel: mbarrier pipeline + cross-tile prefetch + fine-grained
// column-bit dependencies. Refill for stage s+2 issued BEFORE the kk0 MMA
// burst. Stage loop unrolled x3 (matches buffer rotation) so s%3 / parity
// selects are compile-time. kinds: 0=UPD0, 1=S(fwd), 2=UPDATE(bwd), 3=OUT(fwd).
// ---------------------------------------------------------------------------
__global__ __launch_bounds__(256, 2)
void vc_persist(float* __restrict__ outp)
{
    extern __shared__ __align__(1024) char smem[];
    __shared__ int sh_t[2];
    __shared__ __align__(8) unsigned long long s_mbar[6];   // full[0..2], empty[3..5]
    const uint32_t sb = smem_u32(smem);
    const uint32_t mb = smem_u32(s_mbar);
    const int tid = threadIdx.x;
    const int wid = tid >> 5, l = tid & 31;
    const int wm = (wid & 1) * 64, wn = (wid >> 1) * 32;

    if (tid == 0) {
#pragma unroll
        for (int b = 0; b < 3; ++b) {
            MBAR_INIT(mb + b * 8, 256);        // full: 1 noinc async-arrive/thread/fill
            MBAR_INIT(mb + 24 + b * 8, 256);   // empty: 1 arrive/thread/consume
        }
    }
    __syncthreads();
    MBAR_ARRIVE(mb + 24);
    MBAR_ARRIVE(mb + 32);
    MBAR_ARRIVE(mb + 40);

    uint32_t ep = 0, fp = 0;   // per-buffer parity bitmasks (persist across tiles)

    const int q = l >> 3, i8 = l & 7;
    const uint32_t rowA0 = (uint32_t)(wm + ((q & 1) << 3) + i8);
    const uint32_t rowB0 = (uint32_t)(wn + ((q >> 1) << 3) + i8);
    const uint32_t cA0 = (uint32_t)((q >> 1) << 4);
    const uint32_t cB0 = (uint32_t)((q & 1) << 4);
    uint32_t offA[2][4], offB[2][2];
#pragma unroll
    for (int kk = 0; kk < 2; ++kk) {
#pragma unroll
        for (int i = 0; i < 4; ++i) {
            const uint32_t row = rowA0 + i * 16, col = cA0 + kk * 32;
            offA[kk][i] = row * 64u + (col ^ (((row >> 1) & 3) << 4));
        }
#pragma unroll
        for (int jj = 0; jj < 2; ++jj) {
            const uint32_t row = rowB0 + jj * 16, col = cB0 + kk * 32;
            offB[kk][jj] = 2u * MATB + row * 64u + (col ^ (((row >> 1) & 3) << 4));
        }
    }

    // cp.async of one stage slice. its 0..3 = A (dep-gated), 4..7 = B (dep-free)
    auto cps = [&](const TI& T, int s, int it0, int it1, bool arrive) {
        const uint32_t base = sb + (uint32_t)(s % 3) * STAGE;
        const int k0 = s * BK;
#pragma unroll
        for (int it = 0; it < 8; ++it) {
            if (it < it0 || it >= it1) continue;
            const int reg = it >> 1;                       // 0=Ah 1=Al 2=Bh 3=Bl
            const int oo = ((it & 1) << 8) + tid;          // 0..511
            const int r = oo >> 2, c = oo & 3;
            const __nv_bfloat16* mat = (reg == 0) ? T.Ah : (reg == 1) ? T.Al
                                     : (reg == 2) ? T.Bh : T.Bl;
            const int grow = ((reg < 2) ? T.bm : T.bn) + r;
            const uint32_t dst = base + (uint32_t)reg * MATB + (uint32_t)(r * 64)
                               + (uint32_t)((c * 16) ^ (((r >> 1) & 3) << 4));
            cp16(dst, mat + (size_t)grow * (size_t)T.K + k0 + c * 8);
        }
        if (arrive) CPA_MBAR_ARRIVE(mb + (uint32_t)(s % 3) * 8);
    };
    auto wait_empty = [&](int s) {
        const uint32_t b = (uint32_t)(s % 3);
        MBAR_WAIT_PARITY(mb + 24 + b * 8, (ep >> b) & 1u);
        ep ^= 1u << b;
    };

    // ---- first ticket
    if (tid == 0) sh_t[0] = (int)atomicAdd(&g_ticket, 1u);
    __syncthreads();
    int nb = 1;
    if (sh_t[0] >= TOTAL_TILES) return;
    TI cu; decode_t(sh_t[0], cu);
    uint32_t seen = cu.p ? 0u : ~0u;
    wait_empty(0); cps(cu, 0, 4, 8, false);
    wait_empty(1); cps(cu, 1, 4, 8, false);
    gate_f(cu, 0, seen);
    cps(cu, 0, 0, 4, true);
    cps(cu, 1, 0, 4, true);

    for (;;) {
        // ---- accumulators
        float acc[4][4][4];
#pragma unroll
        for (int i = 0; i < 4; ++i)
#pragma unroll
            for (int j = 0; j < 4; ++j)
#pragma unroll
                for (int r = 0; r < 4; ++r) acc[i][j][r] = 0.f;

        const int NSl = cu.NSl;
#pragma unroll 3
        for (int s = 0; s < NSl; ++s) {
            const uint32_t b = (uint32_t)(s % 3);
            MBAR_WAIT_PARITY(mb + b * 8, (fp >> b) & 1u);
            fp ^= 1u << b;
            const uint32_t base = sb + b * STAGE;

            // ---- kk = 0 loads
            uint32_t bh0[2][4], bl0[2][4], ah0[4][4], al0[4][4];
#pragma unroll
            for (int jj = 0; jj < 2; ++jj) {
                ldsm4(bh0[jj], base + offB[0][jj]);
                ldsm4(bl0[jj], base + offB[0][jj] + MATB);
            }
#pragma unroll
            for (int i = 0; i < 4; ++i) {
                ldsm4(ah0[i], base + offA[0][i]);
                ldsm4(al0[i], base + offA[0][i] + MATB);
            }

            // ---- refill stage s+2 BEFORE the MMA bursts (cp.asyncs overlap MMAs)
            if (s + 2 < NSl) {
                gate_f(cu, (s + 2) >> 2, seen);
                wait_empty(s + 2);
                cps(cu, s + 2, 0, 8, true);
            }

            // ---- kk = 0 MMAs
#pragma unroll
            for (int i = 0; i < 4; ++i)
#pragma unroll
                for (int j = 0; j < 4; ++j) {
                    const uint32_t* bhp = &bh0[j >> 1][(j & 1) * 2];
                    const uint32_t* blp = &bl0[j >> 1][(j & 1) * 2];
                    mma16816(acc[i][j], ah0[i], bhp);
                    mma16816(acc[i][j], ah0[i], blp);
                    mma16816(acc[i][j], al0[i], bhp);
                }

            // ---- kk = 1 loads, release buffer, then kk = 1 MMAs
            uint32_t bh1[2][4], bl1[2][4], ah1[4][4], al1[4][4];
#pragma unroll
            for (int jj = 0; jj < 2; ++jj) {
                ldsm4(bh1[jj], base + offB[1][jj]);
                ldsm4(bl1[jj], base + offB[1][jj] + MATB);
            }
#pragma unroll
            for (int i = 0; i < 4; ++i) {
                ldsm4(ah1[i], base + offA[1][i]);
                ldsm4(al1[i], base + offA[1][i] + MATB);
            }
            MBAR_ARRIVE(mb + 24 + b * 8);          // done reading buffer b
#pragma unroll
            for (int i = 0; i < 4; ++i)
#pragma unroll
                for (int j = 0; j < 4; ++j) {
                    const uint32_t* bhp = &bh1[j >> 1][(j & 1) * 2];
                    const uint32_t* blp = &bl1[j >> 1][(j & 1) * 2];
                    mma16816(acc[i][j], ah1[i], bhp);
                    mma16816(acc[i][j], ah1[i], blp);
                    mma16816(acc[i][j], al1[i], bhp);
                }
        }

        // ---- fetch next ticket and prefetch its dep-free B tiles BEFORE epilogue
        if (tid == 0) sh_t[nb] = (int)atomicAdd(&g_ticket, 1u);
        __syncthreads();
        const int tn = sh_t[nb]; nb ^= 1;
        TI nx;
        const bool nxv = (tn < TOTAL_TILES);
        if (nxv) {
            decode_t(tn, nx);
            wait_empty(0); cps(nx, 0, 4, 8, false);
            wait_empty(1); cps(nx, 1, 4, 8, false);
        }

        // ---- fused epilogue for cu (overlaps with next-B cp.asyncs)
        {
            const int kind = cu.kind, N = cu.N, bm = cu.bm, bn = cu.bn;
#pragma unroll
            for (int i = 0; i < 4; ++i) {
                const int row0 = bm + wm + i * 16 + (l >> 2);
#pragma unroll
                for (int j = 0; j < 4; ++j) {
                    const int col = bn + wn + j * 8 + (l & 3) * 2;
#pragma unroll
                    for (int h = 0; h < 2; ++h) {
                        const int row = row0 + h * 8;
                        const float v0 = acc[i][j][h * 2], v1 = acc[i][j][h * 2 + 1];
                        const size_t gi = (size_t)row * (size_t)N + (size_t)col;
                        if (kind == 1) {
                            const float2 av = *(const float2*)(g_a + gi);
                            const float s0 = -0.05f * __expf(-v0) * av.x;
                            const float s1 = -0.05f * __expf(-v1) * av.y;
                            unsigned short h0, l0, h1, l1;
                            split2(s0, h0, l0); split2(s1, h1, l1);
                            *(uint32_t*)(g_sh + gi) = (uint32_t)h0 | ((uint32_t)h1 << 16);
                            *(uint32_t*)(g_sl + gi) = (uint32_t)l0 | ((uint32_t)l1 << 16);
                        } else if (kind == 3) {
                            const float2 av = *(const float2*)(g_a + gi);
                            float2 o;
                            o.x = 0.05f * (1.0f + __expf(-v0)) * av.x;
                            o.y = 0.05f * (1.0f + __expf(-v1)) * av.y;
                            *(float2*)(outp + gi) = o;
                        } else if (kind == 0) {
                            float vv[2] = {v0, v1};
                            float a1o[2], a2o[2];
                            unsigned short nh[2], nl[2];
#pragma unroll
                            for (int k = 0; k < 2; ++k) {
                                const float g = vv[k];
                                const float a1 = 0.1f * g * g;
                                const float inv = rsqrtf(a1 + 1e-8f);
                                const float st = 0.009f * g * inv;
                                const float a2 = -st;
                                const float cand = -st;
                                const float tt = 0.0009f * inv;
                                const float xn = fmaxf(cand - tt, 0.f) + fminf(cand + tt, 0.f) + 0.9f * a2;
                                a1o[k] = a1; a2o[k] = a2;
                                split2(xn, nh[k], nl[k]);
                            }
                            *(float2*)(g_acc1 + gi) = make_float2(a1o[0], a1o[1]);
                            *(float2*)(g_acc2 + gi) = make_float2(a2o[0], a2o[1]);
                            *(uint32_t*)(g_xh + gi) = (uint32_t)nh[0] | ((uint32_t)nh[1] << 16);
                            *(uint32_t*)(g_xl + gi) = (uint32_t)nl[0] | ((uint32_t)nl[1] << 16);
                        } else {
                            float2 A1 = *(float2*)(g_acc1 + gi);
                            float2 A2 = *(float2*)(g_acc2 + gi);
                            const uint32_t XH = *(uint32_t*)(g_xh + gi);
                            const uint32_t XL = *(uint32_t*)(g_xl + gi);
                            float vv[2]  = {v0, v1};
                            float a1v[2] = {A1.x, A1.y};
                            float a2v[2] = {A2.x, A2.y};
                            unsigned short hs[2] = {(unsigned short)(XH & 0xFFFF), (unsigned short)(XH >> 16)};
                            unsigned short ls[2] = {(unsigned short)(XL & 0xFFFF), (unsigned short)(XL >> 16)};
                            unsigned short nh[2], nl[2];
#pragma unroll
                            for (int k = 0; k < 2; ++k) {
                                const float x = bfu(hs[k]) + bfu(ls[k]);
                                const float g = vv[k] + 0.02f * x + 0.1f * x * rsqrtf(x * x + 1e-6f);
                                const float a1 = 0.9f * a1v[k] + 0.1f * g * g;
                                const float inv = rsqrtf(a1 + 1e-8f);
                                const float st = 0.009f * g * inv;
                                const float a2 = 0.9f * a2v[k] - st;
                                const float cand = x - st;
                                const float tt = 0.0009f * inv;
                                const float xn = fmaxf(cand - tt, 0.f) + fminf(cand + tt, 0.f) + 0.9f * a2;
                                a1v[k] = a1; a2v[k] = a2;
                                split2(xn, nh[k], nl[k]);
                            }
                            *(float2*)(g_acc1 + gi) = make_float2(a1v[0], a1v[1]);
                            *(float2*)(g_acc2 + gi) = make_float2(a2v[0], a2v[1]);
                            *(uint32_t*)(g_xh + gi) = (uint32_t)nh[0] | ((uint32_t)nh[1] << 16);
                            *(uint32_t*)(g_xl + gi) = (uint32_t)nl[0] | ((uint32_t)nl[1] << 16);
                        }
                    }
                }
            }
        }

        // ---- publish tile completion (column bit)
        __threadfence();
        __syncthreads();
        if (tid == 0) atomicOr(&g_bits[cu.p][cu.band], 1u << cu.colt);

        if (!nxv) break;

        // ---- gated A loads for the next tile
        seen = nx.p ? 0u : ~0u;
        gate_f(nx, 0, seen);
        cps(nx, 0, 0, 4, true);
        cps(nx, 1, 0, 4, true);
        cu = nx;
    }
}

// ---------------------------------------------------------------- small kernels
__global__ void reset_k()
{
    const int i = threadIdx.x;
    if (i == 0) g_ticket = 0;
    if (i < N_PHASES * 32) ((unsigned int*)g_bits)[i] = 0;
}

__global__ void prep_k(const float* __restrict__ in)
{
    size_t i = (size_t)blockIdx.x * blockDim.x + threadIdx.x;   // 2097152 float4
    float4 v = ((const float4*)in)[i];
    float4 a;
    a.x = sqrtf(v.x * v.x + 1e-6f);
    a.y = sqrtf(v.y * v.y + 1e-6f);
    a.z = sqrtf(v.z * v.z + 1e-6f);
    a.w = sqrtf(v.w * v.w + 1e-6f);
    ((float4*)g_a)[i] = a;
    unsigned short h[4], l[4];
    split2(-0.05f * a.x, h[0], l[0]);
    split2(-0.05f * a.y, h[1], l[1]);
    split2(-0.05f * a.z, h[2], l[2]);
    split2(-0.05f * a.w, h[3], l[3]);
    uint2 H, L;
    H.x = (uint32_t)h[0] | ((uint32_t)h[1] << 16); H.y = (uint32_t)h[2] | ((uint32_t)h[3] << 16);
    L.x = (uint32_t)l[0] | ((uint32_t)l[1] << 16); L.y = (uint32_t)l[2] | ((uint32_t)l[3] << 16);
    ((uint2*)g_sh)[i] = H;
    ((uint2*)g_sl)[i] = L;
}

// W [4096,2048] -> wb (same layout, bf16 hi/lo) and wf (transposed [2048,4096])
__global__ void convW_k(const float* __restrict__ W)
{
    __shared__ float t[32][33];
    const int n0 = blockIdx.x * 32, k0 = blockIdx.y * 32;
    const int tx = threadIdx.x, ty = threadIdx.y;   // 32 x 8
#pragma unroll
    for (int i = 0; i < 4; ++i) {
        int k = k0 + ty + i * 8;
        float w = W[(size_t)k * IN_DIM + n0 + tx];
        t[ty + i * 8][tx] = w;
        unsigned short h, l; split2(w, h, l);
        g_wbh[(size_t)k * IN_DIM + n0 + tx] = __ushort_as_bfloat16(h);
        g_wbl[(size_t)k * IN_DIM + n0 + tx] = __ushort_as_bfloat16(l);
    }
    __syncthreads();
#pragma unroll
    for (int i = 0; i < 4; ++i) {
        int n = n0 + ty + i * 8;
        float w = t[tx][ty + i * 8];                 // = W[k0+tx, n]
        unsigned short h, l; split2(w, h, l);
        g_wfh[(size_t)n * OUT_DIM + k0 + tx] = __ushort_as_bfloat16(h);
        g_wfl[(size_t)n * OUT_DIM + k0 + tx] = __ushort_as_bfloat16(l);
    }
}

// ---------------------------------------------------------------- launcher
extern "C" void kernel_launch(void* const* d_in, const int* in_sizes, int n_in,
                              void* d_out, int out_size)
{
    const float* inp = (const float*)d_in[0];   // [4096, 2048]
    const float* W   = (const float*)d_in[1];   // [4096, 2048]
    float* out = (float*)d_out;                 // [4096, 2048]

    cudaFuncSetAttribute(vc_persist, cudaFuncAttributeMaxDynamicSharedMemorySize, SMEM_TOTAL);

    int sms = 148;
    cudaDeviceGetAttribute(&sms, cudaDevAttrMultiProcessorCount, 0);

    reset_k<<<1, 1024>>>();
    prep_k<<<8192, 256>>>(inp);
    convW_k<<<dim3(IN_DIM / 32, OUT_DIM / 32), dim3(32, 8)>>>(W);

    vc_persist<<<2 * sms, 256, SMEM_TOTAL>>>(out);
}

// round 16
// speedup vs baseline: 1.0297x; 1.0297x over previous
#include <cuda_runtime.h>
#include <cuda_bf16.h>
#include <math.h>
#include <stdint.h>

// ---------------------------------------------------------------- constants
#define BATCH   4096
#define IN_DIM  2048
#define OUT_DIM 4096

#define BM 128
#define BN 128
#define BK 32                    // bf16 elements per stage (64B rows)
#define MATB 8192u               // one 128x32 bf16 matrix in smem
#define STAGE 32768u             // Ah | Al | Bh | Bl
#define SMEM_TOTAL (3 * 32768)   // 96KB dynamic -> 2 CTAs/SM

#define N_PHASES 18
#define TOTAL_TILES 13824

// ---------------------------------------------------------------- state
__device__ float g_acc1[(size_t)BATCH*OUT_DIM];
__device__ float g_acc2[(size_t)BATCH*OUT_DIM];
__device__ float g_a   [(size_t)BATCH*IN_DIM];
__device__ __nv_bfloat16 g_xh [(size_t)BATCH*OUT_DIM];
__device__ __nv_bfloat16 g_xl [(size_t)BATCH*OUT_DIM];
__device__ __nv_bfloat16 g_sh [(size_t)BATCH*IN_DIM];
__device__ __nv_bfloat16 g_sl [(size_t)BATCH*IN_DIM];
__device__ __nv_bfloat16 g_wbh[(size_t)OUT_DIM*IN_DIM];   // W  [4096,2048]  (backward B)
__device__ __nv_bfloat16 g_wbl[(size_t)OUT_DIM*IN_DIM];
__device__ __nv_bfloat16 g_wfh[(size_t)IN_DIM*OUT_DIM];   // W^T [2048,4096] (forward B)
__device__ __nv_bfloat16 g_wfl[(size_t)IN_DIM*OUT_DIM];

__device__ unsigned int g_ticket;
__device__ unsigned int g_bits[N_PHASES][32];   // per (phase,band): bit c = col tile c done

// phase p tile offsets. p0 = UPD0 (1024); p=2i-1 fwd (512), p=2i bwd (1024); p17 = OUT (512)
__constant__ int c_off[N_PHASES + 1] = {
    0, 1024, 1536, 2560, 3072, 4096, 4608, 5632, 6144, 7168,
    7680, 8704, 9216, 10240, 10752, 11776, 12288, 13312, 13824};

// ---------------------------------------------------------------- helpers
__device__ __forceinline__ uint32_t smem_u32(const void* p) {
    uint32_t a;
    asm("{ .reg .u64 t; cvta.to.shared.u64 t, %1; cvt.u32.u64 %0, t; }" : "=r"(a) : "l"(p));
    return a;
}

__device__ __forceinline__ void cp16(uint32_t dst, const void* src) {
    asm volatile("cp.async.cg.shared.global [%0], [%1], 16;" :: "r"(dst), "l"(src));
}

__device__ __forceinline__ uint32_t ldcg(const unsigned int* p) {
    uint32_t v;
    asm volatile("ld.global.cg.u32 %0, [%1];" : "=r"(v) : "l"(p));
    return v;
}

#define MBAR_INIT(addr, cnt) \
    asm volatile("mbarrier.init.shared.b64 [%0], %1;" :: "r"((uint32_t)(addr)), "r"((uint32_t)(cnt)) : "memory")

#define MBAR_ARRIVE(addr) \
    asm volatile("mbarrier.arrive.shared.b64 _, [%0];" :: "r"((uint32_t)(addr)) : "memory")

// .noinc: async completion decrements the base count.
#define CPA_MBAR_ARRIVE(addr) \
    asm volatile("cp.async.mbarrier.arrive.noinc.shared.b64 [%0];" :: "r"((uint32_t)(addr)) : "memory")

#define MBAR_WAIT_PARITY(mbar_smem_addr, phase_parity) do { \
    uint32_t _mbar = (uint32_t)(mbar_smem_addr); \
    uint32_t _parity = (uint32_t)(phase_parity); \
    uint32_t _done; \
    asm volatile( \
        "{\n\t.reg .pred p;\n\t" \
        "mbarrier.try_wait.parity.acquire.cta.shared::cta.b64 p, [%1], %2;\n\t" \
        "selp.b32 %0, 1, 0, p;\n\t}" \
        : "=r"(_done) : "r"(_mbar), "r"(_parity) : "memory"); \
    if (!_done) { \
        asm volatile( \
            "{\n\t.reg .pred P1;\n\t" \
            "WAIT_LOOP_%=:\n\t" \
            "mbarrier.try_wait.parity.acquire.cta.shared::cta.b64 P1, [%0], %1, 0x989680;\n\t" \
            "@P1 bra.uni WAIT_DONE_%=;\n\t" \
            "bra.uni WAIT_LOOP_%=;\n\t" \
            "WAIT_DONE_%=:\n\t}" \
            :: "r"(_mbar), "r"(_parity) : "memory"); \
    } \
} while(0)

__device__ __forceinline__ void ldsm4(uint32_t* d, uint32_t addr) {
    asm volatile("ldmatrix.sync.aligned.m8n8.x4.shared.b16 {%0,%1,%2,%3}, [%4];"
                 : "=r"(d[0]), "=r"(d[1]), "=r"(d[2]), "=r"(d[3]) : "r"(addr));
}

__device__ __forceinline__ void mma16816(float* c, const uint32_t* a, const uint32_t* b) {
    asm volatile("mma.sync.aligned.m16n8k16.row.col.f32.bf16.bf16.f32 "
                 "{%0,%1,%2,%3}, {%4,%5,%6,%7}, {%8,%9}, {%0,%1,%2,%3};"
                 : "+f"(c[0]), "+f"(c[1]), "+f"(c[2]), "+f"(c[3])
                 : "r"(a[0]), "r"(a[1]), "r"(a[2]), "r"(a[3]), "r"(b[0]), "r"(b[1]));
}

__device__ __forceinline__ float bfu(unsigned short u) {
    return __bfloat162float(__ushort_as_bfloat16(u));
}
__device__ __forceinline__ void split2(float v, unsigned short& h, unsigned short& l) {
    __nv_bfloat16 hb = __float2bfloat16_rn(v);
    __nv_bfloat16 lb = __float2bfloat16_rn(v - __bfloat162float(hb));
    h = __bfloat16_as_ushort(hb);
    l = __bfloat16_as_ushort(lb);
}

// ---------------------------------------------------------------- tile info
struct TI {
    const __nv_bfloat16 *Ah, *Al, *Bh, *Bl;
    int p, band, colt, kind, K, N, bm, bn, NSl;
};

__device__ __forceinline__ void decode_t(int t, TI& T) {
    int p = 0;
    while (t >= c_off[p + 1]) ++p;
    const int idx = t - c_off[p];
    const int kind = (p == 0) ? 0 : (p == 17) ? 3 : ((p & 1) ? 1 : 2);
    const bool fwd = (kind == 1) || (kind == 3);
    const int band = fwd ? (idx >> 4) : (idx >> 5);
    T.p = p; T.band = band; T.kind = kind;
    T.colt = idx - (fwd ? (band << 4) : (band << 5));
    T.bm = band * BM; T.bn = T.colt * BN;
    T.K = fwd ? OUT_DIM : IN_DIM;
    T.N = fwd ? IN_DIM : OUT_DIM;
    T.NSl = T.K >> 5;
    if (fwd) { T.Ah = g_xh; T.Al = g_xl; T.Bh = g_wfh; T.Bl = g_wfl; }
    else     { T.Ah = g_sh; T.Al = g_sl; T.Bh = g_wbh; T.Bl = g_wbl; }
}

// dependency gate: wait until producer column bit 'grp' of prev phase is set.
__device__ __forceinline__ void gate_f(const TI& T, int grp, uint32_t& seen) {
    const uint32_t bit = 1u << grp;
    if (seen & bit) return;
    const unsigned int* addr = &g_bits[T.p - 1][T.band];
    uint32_t v = ldcg(addr);
    while (!(v & bit)) { __nanosleep(64); v = ldcg(addr); }
    seen = v;
}

// ---------------------------------------------------------------------------
// Persistent kernel: mbarrier pipeline + cross-tile prefetch + fine-grained
// column-bit dependencies. Refill for stage s+2 is issued BEFORE the kk0 MMA
// burst (cp.asyncs overlap the MMAs; only kk1 LDSM + empty-arrive sit between
// the two MMA bursts). kinds: 0=UPD0, 1=S(fwd), 2=UPDATE(bwd), 3=OUT(fwd).
// ---------------------------------------------------------------------------
__global__ __launch_bounds__(256, 2)
void vc_persist(float* __restrict__ outp)
{
    extern __shared__ __align__(1024) char smem[];
    __shared__ int sh_t[2];
    __shared__ __align__(8) unsigned long long s_mbar[6];   // full[0..2], empty[3..5]
    const uint32_t sb = smem_u32(smem);
    const uint32_t mb = smem_u32(s_mbar);
    const int tid = threadIdx.x;
    const int wid = tid >> 5, l = tid & 31;
    const int wm = (wid & 1) * 64, wn = (wid >> 1) * 32;

    if (tid == 0) {
#pragma unroll
        for (int b = 0; b < 3; ++b) {
            MBAR_INIT(mb + b * 8, 256);        // full: 1 noinc async-arrive/thread/fill
            MBAR_INIT(mb + 24 + b * 8, 256);   // empty: 1 arrive/thread/consume
        }
    }
    __syncthreads();
    MBAR_ARRIVE(mb + 24);
    MBAR_ARRIVE(mb + 32);
    MBAR_ARRIVE(mb + 40);

    uint32_t ep = 0, fp = 0;   // per-buffer parity bitmasks (persist across tiles)

    const int q = l >> 3, i8 = l & 7;
    const uint32_t rowA0 = (uint32_t)(wm + ((q & 1) << 3) + i8);
    const uint32_t rowB0 = (uint32_t)(wn + ((q >> 1) << 3) + i8);
    const uint32_t cA0 = (uint32_t)((q >> 1) << 4);
    const uint32_t cB0 = (uint32_t)((q & 1) << 4);
    uint32_t offA[2][4], offB[2][2];
#pragma unroll
    for (int kk = 0; kk < 2; ++kk) {
#pragma unroll
        for (int i = 0; i < 4; ++i) {
            const uint32_t row = rowA0 + i * 16, col = cA0 + kk * 32;
            offA[kk][i] = row * 64u + (col ^ (((row >> 1) & 3) << 4));
        }
#pragma unroll
        for (int jj = 0; jj < 2; ++jj) {
            const uint32_t row = rowB0 + jj * 16, col = cB0 + kk * 32;
            offB[kk][jj] = 2u * MATB + row * 64u + (col ^ (((row >> 1) & 3) << 4));
        }
    }

    // cp.async of one stage slice. its 0..3 = A (dep-gated), 4..7 = B (dep-free)
    auto cps = [&](const TI& T, int s, int it0, int it1, bool arrive) {
        const uint32_t base = sb + (uint32_t)(s % 3) * STAGE;
        const int k0 = s * BK;
#pragma unroll
        for (int it = 0; it < 8; ++it) {
            if (it < it0 || it >= it1) continue;
            const int reg = it >> 1;                       // 0=Ah 1=Al 2=Bh 3=Bl
            const int oo = ((it & 1) << 8) + tid;          // 0..511
            const int r = oo >> 2, c = oo & 3;
            const __nv_bfloat16* mat = (reg == 0) ? T.Ah : (reg == 1) ? T.Al
                                     : (reg == 2) ? T.Bh : T.Bl;
            const int grow = ((reg < 2) ? T.bm : T.bn) + r;
            const uint32_t dst = base + (uint32_t)reg * MATB + (uint32_t)(r * 64)
                               + (uint32_t)((c * 16) ^ (((r >> 1) & 3) << 4));
            cp16(dst, mat + (size_t)grow * (size_t)T.K + k0 + c * 8);
        }
        if (arrive) CPA_MBAR_ARRIVE(mb + (uint32_t)(s % 3) * 8);
    };
    auto wait_empty = [&](int s) {
        const uint32_t b = (uint32_t)(s % 3);
        MBAR_WAIT_PARITY(mb + 24 + b * 8, (ep >> b) & 1u);
        ep ^= 1u << b;
    };

    // ---- first ticket
    if (tid == 0) sh_t[0] = (int)atomicAdd(&g_ticket, 1u);
    __syncthreads();
    int nb = 1;
    if (sh_t[0] >= TOTAL_TILES) return;
    TI cu; decode_t(sh_t[0], cu);
    uint32_t seen = cu.p ? 0u : ~0u;
    wait_empty(0); cps(cu, 0, 4, 8, false);
    wait_empty(1); cps(cu, 1, 4, 8, false);
    gate_f(cu, 0, seen);
    cps(cu, 0, 0, 4, true);
    cps(cu, 1, 0, 4, true);

    for (;;) {
        // ---- accumulators
        float acc[4][4][4];
#pragma unroll
        for (int i = 0; i < 4; ++i)
#pragma unroll
            for (int j = 0; j < 4; ++j)
#pragma unroll
                for (int r = 0; r < 4; ++r) acc[i][j][r] = 0.f;

        const int NSl = cu.NSl;
        for (int s = 0; s < NSl; ++s) {
            const uint32_t b = (uint32_t)(s % 3);
            MBAR_WAIT_PARITY(mb + b * 8, (fp >> b) & 1u);
            fp ^= 1u << b;
            const uint32_t base = sb + b * STAGE;

            // ---- kk = 0 loads
            uint32_t bh0[2][4], bl0[2][4], ah0[4][4], al0[4][4];
#pragma unroll
            for (int jj = 0; jj < 2; ++jj) {
                ldsm4(bh0[jj], base + offB[0][jj]);
                ldsm4(bl0[jj], base + offB[0][jj] + MATB);
            }
#pragma unroll
            for (int i = 0; i < 4; ++i) {
                ldsm4(ah0[i], base + offA[0][i]);
                ldsm4(al0[i], base + offA[0][i] + MATB);
            }

            // ---- refill stage s+2 BEFORE the MMA bursts (cp.asyncs overlap MMAs)
            if (s + 2 < NSl) {
                gate_f(cu, (s + 2) >> 2, seen);
                wait_empty(s + 2);
                cps(cu, s + 2, 0, 8, true);
            }

            // ---- kk = 0 MMAs
#pragma unroll
            for (int i = 0; i < 4; ++i)
#pragma unroll
                for (int j = 0; j < 4; ++j) {
                    const uint32_t* bhp = &bh0[j >> 1][(j & 1) * 2];
                    const uint32_t* blp = &bl0[j >> 1][(j & 1) * 2];
                    mma16816(acc[i][j], ah0[i], bhp);
                    mma16816(acc[i][j], ah0[i], blp);
                    mma16816(acc[i][j], al0[i], bhp);
                }

            // ---- kk = 1 loads, release buffer, then kk = 1 MMAs
            uint32_t bh1[2][4], bl1[2][4], ah1[4][4], al1[4][4];
#pragma unroll
            for (int jj = 0; jj < 2; ++jj) {
                ldsm4(bh1[jj], base + offB[1][jj]);
                ldsm4(bl1[jj], base + offB[1][jj] + MATB);
            }
#pragma unroll
            for (int i = 0; i < 4; ++i) {
                ldsm4(ah1[i], base + offA[1][i]);
                ldsm4(al1[i], base + offA[1][i] + MATB);
            }
            MBAR_ARRIVE(mb + 24 + b * 8);          // done reading buffer b
#pragma unroll
            for (int i = 0; i < 4; ++i)
#pragma unroll
                for (int j = 0; j < 4; ++j) {
                    const uint32_t* bhp = &bh1[j >> 1][(j & 1) * 2];
                    const uint32_t* blp = &bl1[j >> 1][(j & 1) * 2];
                    mma16816(acc[i][j], ah1[i], bhp);
                    mma16816(acc[i][j], ah1[i], blp);
                    mma16816(acc[i][j], al1[i], bhp);
                }
        }

        // ---- fetch next ticket and prefetch its dep-free B tiles BEFORE epilogue
        if (tid == 0) sh_t[nb] = (int)atomicAdd(&g_ticket, 1u);
        __syncthreads();
        const int tn = sh_t[nb]; nb ^= 1;
        TI nx;
        const bool nxv = (tn < TOTAL_TILES);
        if (nxv) {
            decode_t(tn, nx);
            wait_empty(0); cps(nx, 0, 4, 8, false);
            wait_empty(1); cps(nx, 1, 4, 8, false);
        }

        // ---- fused epilogue for cu (overlaps with next-B cp.asyncs)
        {
            const int kind = cu.kind, N = cu.N, bm = cu.bm, bn = cu.bn;
#pragma unroll
            for (int i = 0; i < 4; ++i) {
                const int row0 = bm + wm + i * 16 + (l >> 2);
#pragma unroll
                for (int j = 0; j < 4; ++j) {
                    const int col = bn + wn + j * 8 + (l & 3) * 2;
#pragma unroll
                    for (int h = 0; h < 2; ++h) {
                        const int row = row0 + h * 8;
                        const float v0 = acc[i][j][h * 2], v1 = acc[i][j][h * 2 + 1];
                        const size_t gi = (size_t)row * (size_t)N + (size_t)col;
                        if (kind == 1) {
                            const float2 av = *(const float2*)(g_a + gi);
                            const float s0 = -0.05f * __expf(-v0) * av.x;
                            const float s1 = -0.05f * __expf(-v1) * av.y;
                            unsigned short h0, l0, h1, l1;
                            split2(s0, h0, l0); split2(s1, h1, l1);
                            *(uint32_t*)(g_sh + gi) = (uint32_t)h0 | ((uint32_t)h1 << 16);
                            *(uint32_t*)(g_sl + gi) = (uint32_t)l0 | ((uint32_t)l1 << 16);
                        } else if (kind == 3) {
                            const float2 av = *(const float2*)(g_a + gi);
                            float2 o;
                            o.x = 0.05f * (1.0f + __expf(-v0)) * av.x;
                            o.y = 0.05f * (1.0f + __expf(-v1)) * av.y;
                            *(float2*)(outp + gi) = o;
                        } else if (kind == 0) {
                            float vv[2] = {v0, v1};
                            float a1o[2], a2o[2];
                            unsigned short nh[2], nl[2];
#pragma unroll
                            for (int k = 0; k < 2; ++k) {
                                const float g = vv[k];
                                const float a1 = 0.1f * g * g;
                                const float inv = rsqrtf(a1 + 1e-8f);
                                const float st = 0.009f * g * inv;
                                const float a2 = -st;
                                const float cand = -st;
                                const float tt = 0.0009f * inv;
                                const float xn = fmaxf(cand - tt, 0.f) + fminf(cand + tt, 0.f) + 0.9f * a2;
                                a1o[k] = a1; a2o[k] = a2;
                                split2(xn, nh[k], nl[k]);
                            }
                            *(float2*)(g_acc1 + gi) = make_float2(a1o[0], a1o[1]);
                            *(float2*)(g_acc2 + gi) = make_float2(a2o[0], a2o[1]);
                            *(uint32_t*)(g_xh + gi) = (uint32_t)nh[0] | ((uint32_t)nh[1] << 16);
                            *(uint32_t*)(g_xl + gi) = (uint32_t)nl[0] | ((uint32_t)nl[1] << 16);
                        } else {
                            float2 A1 = *(float2*)(g_acc1 + gi);
                            float2 A2 = *(float2*)(g_acc2 + gi);
                            const uint32_t XH = *(uint32_t*)(g_xh + gi);
                            const uint32_t XL = *(uint32_t*)(g_xl + gi);
                            float vv[2]  = {v0, v1};
                            float a1v[2] = {A1.x, A1.y};
                            float a2v[2] = {A2.x, A2.y};
                            unsigned short hs[2] = {(unsigned short)(XH & 0xFFFF), (unsigned short)(XH >> 16)};
                            unsigned short ls[2] = {(unsigned short)(XL & 0xFFFF), (unsigned short)(XL >> 16)};
                            unsigned short nh[2], nl[2];
#pragma unroll
                            for (int k = 0; k < 2; ++k) {
                                const float x = bfu(hs[k]) + bfu(ls[k]);
                                const float g = vv[k] + 0.02f * x + 0.1f * x * rsqrtf(x * x + 1e-6f);
                                const float a1 = 0.9f * a1v[k] + 0.1f * g * g;
                                const float inv = rsqrtf(a1 + 1e-8f);
                                const float st = 0.009f * g * inv;
                                const float a2 = 0.9f * a2v[k] - st;
                                const float cand = x - st;
                                const float tt = 0.0009f * inv;
                                const float xn = fmaxf(cand - tt, 0.f) + fminf(cand + tt, 0.f) + 0.9f * a2;
                                a1v[k] = a1; a2v[k] = a2;
                                split2(xn, nh[k], nl[k]);
                            }
                            *(float2*)(g_acc1 + gi) = make_float2(a1v[0], a1v[1]);
                            *(float2*)(g_acc2 + gi) = make_float2(a2v[0], a2v[1]);
                            *(uint32_t*)(g_xh + gi) = (uint32_t)nh[0] | ((uint32_t)nh[1] << 16);
                            *(uint32_t*)(g_xl + gi) = (uint32_t)nl[0] | ((uint32_t)nl[1] << 16);
                        }
                    }
                }
            }
        }

        // ---- publish tile completion (column bit)
        __threadfence();
        __syncthreads();
        if (tid == 0) atomicOr(&g_bits[cu.p][cu.band], 1u << cu.colt);

        if (!nxv) break;

        // ---- gated A loads for the next tile
        seen = nx.p ? 0u : ~0u;
        gate_f(nx, 0, seen);
        cps(nx, 0, 0, 4, true);
        cps(nx, 1, 0, 4, true);
        cu = nx;
    }
}

// ---------------------------------------------------------------- small kernels
__global__ void reset_k()
{
    const int i = threadIdx.x;
    if (i == 0) g_ticket = 0;
    if (i < N_PHASES * 32) ((unsigned int*)g_bits)[i] = 0;
}

__global__ void prep_k(const float* __restrict__ in)
{
    size_t i = (size_t)blockIdx.x * blockDim.x + threadIdx.x;   // 2097152 float4
    float4 v = ((const float4*)in)[i];
    float4 a;
    a.x = sqrtf(v.x * v.x + 1e-6f);
    a.y = sqrtf(v.y * v.y + 1e-6f);
    a.z = sqrtf(v.z * v.z + 1e-6f);
    a.w = sqrtf(v.w * v.w + 1e-6f);
    ((float4*)g_a)[i] = a;
    unsigned short h[4], l[4];
    split2(-0.05f * a.x, h[0], l[0]);
    split2(-0.05f * a.y, h[1], l[1]);
    split2(-0.05f * a.z, h[2], l[2]);
    split2(-0.05f * a.w, h[3], l[3]);
    uint2 H, L;
    H.x = (uint32_t)h[0] | ((uint32_t)h[1] << 16); H.y = (uint32_t)h[2] | ((uint32_t)h[3] << 16);
    L.x = (uint32_t)l[0] | ((uint32_t)l[1] << 16); L.y = (uint32_t)l[2] | ((uint32_t)l[3] << 16);
    ((uint2*)g_sh)[i] = H;
    ((uint2*)g_sl)[i] = L;
}

// W [4096,2048] -> wb (same layout, bf16 hi/lo) and wf (transposed [2048,4096])
__global__ void convW_k(const float* __restrict__ W)
{
    __shared__ float t[32][33];
    const int n0 = blockIdx.x * 32, k0 = blockIdx.y * 32;
    const int tx = threadIdx.x, ty = threadIdx.y;   // 32 x 8
#pragma unroll
    for (int i = 0; i < 4; ++i) {
        int k = k0 + ty + i * 8;
        float w = W[(size_t)k * IN_DIM + n0 + tx];
        t[ty + i * 8][tx] = w;
        unsigned short h, l; split2(w, h, l);
        g_wbh[(size_t)k * IN_DIM + n0 + tx] = __ushort_as_bfloat16(h);
        g_wbl[(size_t)k * IN_DIM + n0 + tx] = __ushort_as_bfloat16(l);
    }
    __syncthreads();
#pragma unroll
    for (int i = 0; i < 4; ++i) {
        int n = n0 + ty + i * 8;
        float w = t[tx][ty + i * 8];                 // = W[k0+tx, n]
        unsigned short h, l; split2(w, h, l);
        g_wfh[(size_t)n * OUT_DIM + k0 + tx] = __ushort_as_bfloat16(h);
        g_wfl[(size_t)n * OUT_DIM + k0 + tx] = __ushort_as_bfloat16(l);
    }
}

// ---------------------------------------------------------------- launcher
extern "C" void kernel_launch(void* const* d_in, const int* in_sizes, int n_in,
                              void* d_out, int out_size)
{
    const float* inp = (const float*)d_in[0];   // [4096, 2048]
    const float* W   = (const float*)d_in[1];   // [4096, 2048]
    float* out = (float*)d_out;                 // [4096, 2048]

    cudaFuncSetAttribute(vc_persist, cudaFuncAttributeMaxDynamicSharedMemorySize, SMEM_TOTAL);

    int sms = 148;
    cudaDeviceGetAttribute(&sms, cudaDevAttrMultiProcessorCount, 0);

    reset_k<<<1, 1024>>>();
    prep_k<<<8192, 256>>>(inp);
    convW_k<<<dim3(IN_DIM / 32, OUT_DIM / 32), dim3(32, 8)>>>(W);

    vc_persist<<<2 * sms, 256, SMEM_TOTAL>>>(out);
}